// round 1
// baseline (speedup 1.0000x reference)
#include <cuda_runtime.h>
#include <math.h>

#define Bb   64
#define NCc  5
#define Ll   20
#define Fr   20
#define Cd   8192
#define Ed   300
#define Hh   512
#define G4   (4*Hh)      // 2048
#define ROWS_T (Bb*NCc)  // 320
#define MV   (Bb*Fr)     // 1280
#define MT   (Bb*NCc*Ll) // 6400

// ---------------- scratch (device globals; no cudaMalloc allowed) ----------------
__device__ float g_Xv[MV * G4];          // video input projections (+b_v1)
__device__ float g_emb[(size_t)MT * Ed]; // gathered embeddings
__device__ float g_Xt[(size_t)MT * G4];  // text input projections (+b_t1)
__device__ float g_vh1[2][Bb*Hh], g_vc1[2][Bb*Hh], g_vh2[2][Bb*Hh], g_vc2[2][Bb*Hh];
__device__ float g_th1[2][ROWS_T*Hh], g_tc1[2][ROWS_T*Hh], g_th2[2][ROWS_T*Hh], g_tc2[2][ROWS_T*Hh];
__device__ float g_wc[2*Hh];
__device__ float g_bc;
__device__ float g_outbuf[ROWS_T];

__device__ __forceinline__ float sigf(float x){ return 1.0f/(1.0f+expf(-x)); }

// ---------------- generic GEMM:  C[M,N] = A[M,K] @ W[N,K]^T + bias[N] ----------------
// BM=BN=64, BK=16, 256 threads, 4x4 register tile. M%64==0, N%64==0 assumed.
template<bool GUARD_K>
__global__ __launch_bounds__(256)
void gemm_bias(const float* __restrict__ A, const float* __restrict__ W,
               const float* __restrict__ bias, float* __restrict__ C,
               int M, int N, int K)
{
    __shared__ float As[16][65];
    __shared__ float Bs[16][65];
    const int tid = threadIdx.x;
    const int tx = tid & 15, ty = tid >> 4;
    const int m0 = blockIdx.y * 64, n0 = blockIdx.x * 64;

    float acc[4][4];
#pragma unroll
    for (int i=0;i<4;i++)
#pragma unroll
        for (int j=0;j<4;j++) acc[i][j]=0.f;

    const int ktiles = (K + 15) >> 4;
    for (int kt = 0; kt < ktiles; kt++) {
        const int k0 = kt << 4;
        if (GUARD_K) {
#pragma unroll
            for (int i = 0; i < 4; i++) {
                int idx = tid + i * 256;
                int m = idx >> 4, k = idx & 15;
                bool ok = (k0 + k) < K;
                As[k][m] = ok ? A[(long)(m0 + m) * K + k0 + k] : 0.f;
                Bs[k][m] = ok ? W[(long)(n0 + m) * K + k0 + k] : 0.f;
            }
        } else {
            int m = tid >> 2, kq = (tid & 3) << 2;
            float4 av = *(const float4*)&A[(long)(m0+m)*K + k0 + kq];
            As[kq+0][m]=av.x; As[kq+1][m]=av.y; As[kq+2][m]=av.z; As[kq+3][m]=av.w;
            float4 bv = *(const float4*)&W[(long)(n0+m)*K + k0 + kq];
            Bs[kq+0][m]=bv.x; Bs[kq+1][m]=bv.y; Bs[kq+2][m]=bv.z; Bs[kq+3][m]=bv.w;
        }
        __syncthreads();
#pragma unroll
        for (int k = 0; k < 16; k++) {
            float a[4], b[4];
#pragma unroll
            for (int i=0;i<4;i++) a[i] = As[k][ty*4+i];
#pragma unroll
            for (int j=0;j<4;j++) b[j] = Bs[k][tx*4+j];
#pragma unroll
            for (int i=0;i<4;i++)
#pragma unroll
                for (int j=0;j<4;j++) acc[i][j] += a[i]*b[j];
        }
        __syncthreads();
    }
#pragma unroll
    for (int i=0;i<4;i++) {
        long m = m0 + ty*4 + i;
#pragma unroll
        for (int j=0;j<4;j++) {
            int n = n0 + tx*4 + j;
            C[m * N + n] = acc[i][j] + bias[n];
        }
    }
}

// ---------------- fused LSTM cell: gates = A1@W1^T (+ A2@W2^T) (+xpre) (+bias) ----------------
// Block computes a [BM batch rows] x [32 hidden units x 4 gates] tile, then applies
// the full LSTM update in the epilogue. K=512 for each GEMM term.
// Grid: (Hh/32, batch/BM). 256 threads. BM = 16*TM.
template<int BM, int TM>
__global__ __launch_bounds__(256)
void lstm_cell(const float* __restrict__ A1, const float* __restrict__ W1,
               const float* __restrict__ A2, const float* __restrict__ W2,
               const float* __restrict__ xpre, int xstride,
               const float* __restrict__ bias,
               const float* __restrict__ hprev, const float* __restrict__ cprev,
               float* __restrict__ hout, float* __restrict__ cout,
               const int* __restrict__ lens, int t, int ncPerB)
{
    __shared__ float As[16][BM+1];
    __shared__ float Ws[16][129];
    const int tid = threadIdx.x;
    const int tx = tid & 15, ty = tid >> 4;
    const int j0 = blockIdx.x * 32;
    const int m0 = blockIdx.y * BM;

    float acc[TM][2][4];
#pragma unroll
    for (int i=0;i<TM;i++)
#pragma unroll
        for (int j=0;j<2;j++)
#pragma unroll
            for (int g=0;g<4;g++) acc[i][j][g]=0.f;

    for (int phase = 0; phase < 2; phase++) {
        const float* A = phase ? A2 : A1;
        const float* W = phase ? W2 : W1;
        if (phase && A2 == nullptr) break;
        for (int kt = 0; kt < Hh/16; kt++) {
            const int k0 = kt << 4;
            // load A tile [BM x 16] -> As[k][m]
#pragma unroll
            for (int i = 0; i < (BM*16)/256; i++) {
                int idx = tid + i * 256;
                int m = idx >> 4, k = idx & 15;
                As[k][m] = A[(m0 + m) * Hh + k0 + k];
            }
            // load W tile: 4 gates x 32 units x 16 k -> Ws[k][g*32+jj]
#pragma unroll
            for (int l = 0; l < 2; l++) {
                int slot = tid + l * 256;
                int r = slot >> 2, kq = (slot & 3) << 2;
                int wrow = ((r >> 5) << 9) + j0 + (r & 31);  // gate*512 + j
                float4 v = *(const float4*)&W[wrow * Hh + k0 + kq];
                Ws[kq+0][r]=v.x; Ws[kq+1][r]=v.y; Ws[kq+2][r]=v.z; Ws[kq+3][r]=v.w;
            }
            __syncthreads();
#pragma unroll
            for (int k = 0; k < 16; k++) {
                float a[TM];
#pragma unroll
                for (int i=0;i<TM;i++) a[i] = As[k][ty*TM+i];
                float w[2][4];
#pragma unroll
                for (int g=0; g<4; g++) {
                    w[0][g] = Ws[k][g*32 + tx*2 + 0];
                    w[1][g] = Ws[k][g*32 + tx*2 + 1];
                }
#pragma unroll
                for (int i=0;i<TM;i++)
#pragma unroll
                    for (int j=0;j<2;j++)
#pragma unroll
                        for (int g=0;g<4;g++) acc[i][j][g] += a[i]*w[j][g];
            }
            __syncthreads();
        }
    }

    // epilogue: LSTM gate math (+ ragged mask)
#pragma unroll
    for (int i=0;i<TM;i++) {
        int m = m0 + ty*TM + i;
        bool masked = (lens != nullptr) && (t >= lens[m / ncPerB]);
#pragma unroll
        for (int j=0;j<2;j++) {
            int jj = j0 + tx*2 + j;
            float pi = acc[i][j][0], pf = acc[i][j][1], pg = acc[i][j][2], po = acc[i][j][3];
            if (bias) { pi += bias[jj]; pf += bias[Hh+jj]; pg += bias[2*Hh+jj]; po += bias[3*Hh+jj]; }
            if (xpre) {
                const float* xr = xpre + (long)m * xstride;
                pi += xr[jj]; pf += xr[Hh+jj]; pg += xr[2*Hh+jj]; po += xr[3*Hh+jj];
            }
            float cold = cprev[m*Hh + jj];
            float cn = sigf(pf)*cold + sigf(pi)*tanhf(pg);
            float hn = sigf(po)*tanhf(cn);
            if (masked) { hn = hprev[m*Hh + jj]; cn = cold; }
            hout[m*Hh + jj] = hn;
            cout[m*Hh + jj] = cn;
        }
    }
}

// ---------------- small helper kernels ----------------
__global__ void zero_vstates() {
    int i = blockIdx.x * blockDim.x + threadIdx.x;
    if (i < Bb*Hh) { g_vh1[0][i]=0.f; g_vc1[0][i]=0.f; g_vh2[0][i]=0.f; g_vc2[0][i]=0.f; }
}

__global__ void embed_gather(const int* __restrict__ q, const float* __restrict__ ew) {
    long i = (long)blockIdx.x * blockDim.x + threadIdx.x;
    if (i < (long)MT * Ed) {
        int r = (int)(i / Ed), k = (int)(i % Ed);
        g_emb[i] = ew[(long)q[r] * Ed + k];
    }
}

__global__ void bcast_init() {
    int i = blockIdx.x * blockDim.x + threadIdx.x;
    if (i < ROWS_T*Hh) {
        int row = i / Hh, k = i % Hh;
        int b = row / NCc;
        g_th1[0][i] = g_vh1[0][b*Hh+k];
        g_tc1[0][i] = g_vc1[0][b*Hh+k];
        g_th2[0][i] = g_vh2[0][b*Hh+k];
        g_tc2[0][i] = g_vc2[0][b*Hh+k];
    }
}

// dec collapses: outputs = sT @ (dec2_w @ dec1_w)^T + (dec1_b . dec2_w + dec2_b)
__global__ void dec_prep(const float* __restrict__ d1w, const float* __restrict__ d1b,
                         const float* __restrict__ d2w, const float* __restrict__ d2b) {
    if (blockIdx.x < 4) {
        int k = blockIdx.x * 256 + threadIdx.x;
        float s = 0.f;
        for (int j = 0; j < 2*Hh; j++) s += d2w[j] * d1w[j*(2*Hh) + k];
        g_wc[k] = s;
    } else {
        __shared__ float red[256];
        float s = 0.f;
        for (int j = threadIdx.x; j < 2*Hh; j += 256) s += d1b[j] * d2w[j];
        red[threadIdx.x] = s; __syncthreads();
        for (int o = 128; o > 0; o >>= 1) {
            if (threadIdx.x < o) red[threadIdx.x] += red[threadIdx.x+o];
            __syncthreads();
        }
        if (threadIdx.x == 0) g_bc = red[0] + d2b[0];
    }
}

__global__ void dec_out(float* __restrict__ dout, int wantOut) {
    int warp = (blockIdx.x * blockDim.x + threadIdx.x) >> 5;
    int lane = threadIdx.x & 31;
    if (warp >= ROWS_T) return;
    const float* h1 = &g_th1[0][warp*Hh];
    const float* h2 = &g_th2[0][warp*Hh];
    float s = 0.f;
    for (int k = lane; k < Hh; k += 32) s += h1[k]*g_wc[k] + h2[k]*g_wc[Hh+k];
#pragma unroll
    for (int o = 16; o > 0; o >>= 1) s += __shfl_down_sync(0xffffffffu, s, o);
    if (lane == 0) {
        float v = s + g_bc;
        g_outbuf[warp] = v;
        if (wantOut) dout[warp] = v;
    }
}

__global__ void argmax_k(float* __restrict__ dout, int off) {
    int b = threadIdx.x;
    if (b < Bb) {
        float best = g_outbuf[b*NCc]; int bi = 0;
        for (int nc = 1; nc < NCc; nc++) {
            float v = g_outbuf[b*NCc + nc];
            if (v > best) { best = v; bi = nc; }
        }
        dout[off + b] = (float)bi;
    }
}

// ---------------- launch ----------------
extern "C" void kernel_launch(void* const* d_in, const int* in_sizes, int n_in,
                              void* d_out, int out_size)
{
    const float* vf     = (const float*)d_in[0];
    const int*   q      = (const int*)  d_in[1];
    const int*   qlen   = (const int*)  d_in[2];
    const float* ew     = (const float*)d_in[3];
    const float* Wih_t1 = (const float*)d_in[4];
    const float* Whh_t1 = (const float*)d_in[5];
    const float* b_t1   = (const float*)d_in[6];
    const float* Wih_t2 = (const float*)d_in[7];
    const float* Whh_t2 = (const float*)d_in[8];
    const float* b_t2   = (const float*)d_in[9];
    const float* Wih_v1 = (const float*)d_in[10];
    const float* Whh_v1 = (const float*)d_in[11];
    const float* b_v1   = (const float*)d_in[12];
    const float* Wih_v2 = (const float*)d_in[13];
    const float* Whh_v2 = (const float*)d_in[14];
    const float* b_v2   = (const float*)d_in[15];
    const float* d1w    = (const float*)d_in[16];
    const float* d1b    = (const float*)d_in[17];
    const float* d2w    = (const float*)d_in[18];
    const float* d2b    = (const float*)d_in[19];
    float* dout = (float*)d_out;

    float *Xv, *emb, *Xt, *vh1, *vc1, *vh2, *vc2, *th1, *tc1, *th2, *tc2;
    cudaGetSymbolAddress((void**)&Xv,  g_Xv);
    cudaGetSymbolAddress((void**)&emb, g_emb);
    cudaGetSymbolAddress((void**)&Xt,  g_Xt);
    cudaGetSymbolAddress((void**)&vh1, g_vh1);
    cudaGetSymbolAddress((void**)&vc1, g_vc1);
    cudaGetSymbolAddress((void**)&vh2, g_vh2);
    cudaGetSymbolAddress((void**)&vc2, g_vc2);
    cudaGetSymbolAddress((void**)&th1, g_th1);
    cudaGetSymbolAddress((void**)&tc1, g_tc1);
    cudaGetSymbolAddress((void**)&th2, g_th2);
    cudaGetSymbolAddress((void**)&tc2, g_tc2);
    const int VS = Bb*Hh;       // video state buffer stride
    const int TS = ROWS_T*Hh;   // text state buffer stride

    // init + big parallel projections
    zero_vstates<<<(Bb*Hh + 255)/256, 256>>>();
    gemm_bias<false><<<dim3(G4/64, MV/64), 256>>>(vf, Wih_v1, b_v1, Xv, MV, G4, Cd);
    embed_gather<<<(int)(((long)MT*Ed + 255)/256), 256>>>(q, ew);
    gemm_bias<true><<<dim3(G4/64, MT/64), 256>>>(emb, Wih_t1, b_t1, Xt, MT, G4, Ed);

    // video 2-layer LSTM over 20 frames (batch 64)
    for (int t = 0; t < Fr; t++) {
        int in = t & 1, out = in ^ 1;
        lstm_cell<16,1><<<dim3(Hh/32, Bb/16), 256>>>(
            vh1 + in*VS, Whh_v1, nullptr, nullptr,
            Xv + t*G4, Fr*G4, nullptr,
            vh1 + in*VS, vc1 + in*VS, vh1 + out*VS, vc1 + out*VS,
            nullptr, 0, 1);
        lstm_cell<16,1><<<dim3(Hh/32, Bb/16), 256>>>(
            vh1 + out*VS, Wih_v2, vh2 + in*VS, Whh_v2,
            nullptr, 0, b_v2,
            vh2 + in*VS, vc2 + in*VS, vh2 + out*VS, vc2 + out*VS,
            nullptr, 0, 1);
    }

    // broadcast final video states (buffer 0 after 20 steps) to 320 text rows
    bcast_init<<<(ROWS_T*Hh + 255)/256, 256>>>();

    // text 2-layer LSTM over 20 words (batch 320, ragged mask)
    for (int t = 0; t < Ll; t++) {
        int in = t & 1, out = in ^ 1;
        lstm_cell<64,4><<<dim3(Hh/32, ROWS_T/64), 256>>>(
            th1 + in*TS, Whh_t1, nullptr, nullptr,
            Xt + t*G4, Ll*G4, nullptr,
            th1 + in*TS, tc1 + in*TS, th1 + out*TS, tc1 + out*TS,
            qlen, t, NCc);
        lstm_cell<64,4><<<dim3(Hh/32, ROWS_T/64), 256>>>(
            th1 + out*TS, Wih_t2, th2 + in*TS, Whh_t2,
            nullptr, 0, b_t2,
            th2 + in*TS, tc2 + in*TS, th2 + out*TS, tc2 + out*TS,
            qlen, t, NCc);
    }

    // decoder (collapsed linear) + argmax
    dec_prep<<<5, 256>>>(d1w, d1b, d2w, d2b);
    int wantOut = (out_size >= ROWS_T) ? 1 : 0;
    dec_out<<<(ROWS_T*32 + 127)/128, 128>>>(dout, wantOut);
    int predOff = -1;
    if (out_size >= ROWS_T + Bb) predOff = ROWS_T;
    else if (out_size == Bb)     predOff = 0;
    if (predOff >= 0) argmax_k<<<1, 64>>>(dout, predOff);
}

// round 5
// speedup vs baseline: 1.2205x; 1.2205x over previous
#include <cuda_runtime.h>
#include <math.h>

#define Bb   64
#define NCc  5
#define Ll   20
#define Fr   20
#define Cd   8192
#define Ed   300
#define Hh   512
#define G4   (4*Hh)      // 2048
#define ROWS_T (Bb*NCc)  // 320
#define MV   (Bb*Fr)     // 1280
#define MT   (Bb*NCc*Ll) // 6400
#define NBLK 160         // persistent grid; <= 2 blocks/SM * 148 SMs guaranteed resident

// ---------------- scratch (device globals; no cudaMalloc allowed) ----------------
__device__ float g_Xv[MV * G4];          // video input projections (+b_v1)
__device__ float g_emb[(size_t)MT * Ed]; // gathered embeddings
__device__ float g_Xt[(size_t)MT * G4];  // text input projections (+b_t1)
__device__ float g_vh1[2][Bb*Hh], g_vc1[2][Bb*Hh], g_vh2[2][Bb*Hh], g_vc2[2][Bb*Hh];
__device__ float g_th1[2][ROWS_T*Hh], g_tc1[2][ROWS_T*Hh], g_th2[2][ROWS_T*Hh], g_tc2[2][ROWS_T*Hh];
__device__ float g_wc[2*Hh];
__device__ float g_bc;
__device__ float g_outbuf[ROWS_T];
__device__ unsigned g_barCnt;
__device__ unsigned g_barGen;

__device__ __forceinline__ float sigf(float x){ return 1.0f/(1.0f+expf(-x)); }

// ---------------- software grid barrier (all NBLK blocks resident by construction) ----
__device__ __forceinline__ void gridsync(unsigned& phase) {
    __threadfence();
    __syncthreads();
    if (threadIdx.x == 0) {
        phase++;
        if (atomicAdd(&g_barCnt, 1u) == NBLK - 1u) {
            g_barCnt = 0u;
            __threadfence();
            atomicExch(&g_barGen, phase);
        } else {
            while (atomicAdd(&g_barGen, 0u) < phase) __nanosleep(64);
        }
    }
    __syncthreads();
}

// ---------------- big GEMM:  C[M,N] = A[M,K] @ W[N,K]^T + bias[N] ----------------
// tile 64(M) x 128(N), BK=16, 256 threads, 8x4 register tile, float4 smem reads.
template<bool GUARD>
__global__ __launch_bounds__(256)
void gemm_big(const float* __restrict__ A, const float* __restrict__ W,
              const float* __restrict__ bias, float* __restrict__ C,
              int M, int N, int K)
{
    __shared__ float As[16][68];
    __shared__ float Bs[16][132];
    const int tid = threadIdx.x;
    const int tx = tid & 31, ty = tid >> 5;   // tx: n-group (4 cols), ty: row group (8 rows)
    const int m0 = blockIdx.y * 64, n0 = blockIdx.x * 128;

    float acc[8][4];
#pragma unroll
    for (int i = 0; i < 8; i++)
#pragma unroll
        for (int j = 0; j < 4; j++) acc[i][j] = 0.f;

    const int ktiles = (K + 15) >> 4;
    for (int kt = 0; kt < ktiles; kt++) {
        const int k0 = kt << 4;
        // load A tile 64x16
        {
            int m = tid >> 2, kq = (tid & 3) << 2;
            if (GUARD) {
#pragma unroll
                for (int i = 0; i < 4; i++) {
                    int k = k0 + kq + i;
                    As[kq + i][m] = (k < K) ? A[(long)(m0 + m) * K + k] : 0.f;
                }
            } else {
                float4 v = *(const float4*)&A[(long)(m0 + m) * K + k0 + kq];
                As[kq + 0][m] = v.x; As[kq + 1][m] = v.y;
                As[kq + 2][m] = v.z; As[kq + 3][m] = v.w;
            }
        }
        // load W tile 128x16
        {
            int r = tid >> 1, kh = (tid & 1) << 3;
#pragma unroll
            for (int q = 0; q < 2; q++) {
                int kq = kh + q * 4;
                if (GUARD) {
#pragma unroll
                    for (int i = 0; i < 4; i++) {
                        int k = k0 + kq + i;
                        Bs[kq + i][r] = (k < K) ? W[(long)(n0 + r) * K + k] : 0.f;
                    }
                } else {
                    float4 v = *(const float4*)&W[(long)(n0 + r) * K + k0 + kq];
                    Bs[kq + 0][r] = v.x; Bs[kq + 1][r] = v.y;
                    Bs[kq + 2][r] = v.z; Bs[kq + 3][r] = v.w;
                }
            }
        }
        __syncthreads();
#pragma unroll
        for (int k = 0; k < 16; k++) {
            float4 b4 = *(const float4*)&Bs[k][tx * 4];
            float4 a0 = *(const float4*)&As[k][ty * 8];
            float4 a1 = *(const float4*)&As[k][ty * 8 + 4];
            float a[8] = {a0.x,a0.y,a0.z,a0.w,a1.x,a1.y,a1.z,a1.w};
            float b[4] = {b4.x,b4.y,b4.z,b4.w};
#pragma unroll
            for (int i = 0; i < 8; i++)
#pragma unroll
                for (int j = 0; j < 4; j++) acc[i][j] += a[i] * b[j];
        }
        __syncthreads();
    }
    float4 bv = *(const float4*)&bias[n0 + tx * 4];
#pragma unroll
    for (int i = 0; i < 8; i++) {
        long m = m0 + ty * 8 + i;
        float4 o = make_float4(acc[i][0] + bv.x, acc[i][1] + bv.y,
                               acc[i][2] + bv.z, acc[i][3] + bv.w);
        *(float4*)&C[m * N + n0 + tx * 4] = o;
    }
}

// ---------------- one LSTM layer update, whole grid cooperates ----------------
// gates = A1@W1^T (+ A2@W2^T) (+xpre) (+bias). W row-major [4*512][512].
// Tile: ROWS batch rows x 32 j's x 4 gates (=128 cols). BK=32. sW[k][jloc*4+g].
template<int ROWS>
__device__ void lstm_stage(
    const float* __restrict__ A1, const float* __restrict__ W1,
    const float* __restrict__ A2, const float* __restrict__ W2,
    const float* __restrict__ xpre, long xstride,
    const float* __restrict__ bias,
    const float* __restrict__ hprev, const float* __restrict__ cprev,
    float* __restrict__ hout, float* __restrict__ cout,
    const int* __restrict__ lens, int t, int M,
    float* sA, float* sW)
{
    constexpr int TM = ROWS / 8;
    constexpr int RP = ROWS + 4;
    const int tid = threadIdx.x;
    const int tx = tid & 31;      // j within tile
    const int ty = tid >> 5;      // row group
    const int ntiles = (M / ROWS) * 16;   // 512/32 j-tiles

    for (int tile = blockIdx.x; tile < ntiles; tile += NBLK) {
        const int m0 = (tile >> 4) * ROWS;
        const int j0 = (tile & 15) * 32;

        // tile skip: all rows masked -> pure state copy (uniform across block)
        if (lens) {
            bool skip = true;
            for (int b = m0 / NCc; b <= (m0 + ROWS - 1) / NCc; b++)
                if (t < lens[b]) { skip = false; break; }
            if (skip) {
                for (int i = tid; i < ROWS * 32; i += 256) {
                    int mm = m0 + (i >> 5), jj = j0 + (i & 31);
                    hout[mm * Hh + jj] = hprev[mm * Hh + jj];
                    cout[mm * Hh + jj] = cprev[mm * Hh + jj];
                }
                continue;
            }
        }

        float acc[TM][4];
#pragma unroll
        for (int i = 0; i < TM; i++)
#pragma unroll
            for (int g = 0; g < 4; g++) acc[i][g] = 0.f;

        for (int ph = 0; ph < 2; ph++) {
            const float* Ap = ph ? A2 : A1;
            const float* Wp = ph ? W2 : W1;
            if (ph && A2 == nullptr) break;
            for (int kt = 0; kt < 16; kt++) {
                const int k0 = kt << 5;
                __syncthreads();
                // A tile: ROWS x 32
                if (ROWS == 32) {
                    int m = tid >> 3, kq = (tid & 7) << 2;
                    float4 v = *(const float4*)&Ap[(m0 + m) * Hh + k0 + kq];
                    sA[(kq + 0) * RP + m] = v.x; sA[(kq + 1) * RP + m] = v.y;
                    sA[(kq + 2) * RP + m] = v.z; sA[(kq + 3) * RP + m] = v.w;
                } else {  // ROWS == 8
                    int m = tid >> 5, k = tid & 31;
                    sA[k * RP + m] = Ap[(m0 + m) * Hh + k0 + k];
                }
                // W tile: 128 cols x 32 k, sW[k][jloc*4+g]
                {
                    int r = tid >> 1, kh = (tid & 1) << 4;
                    int j = r >> 2, g = r & 3;
                    const float* wr = Wp + (g * Hh + j0 + j) * Hh + k0 + kh;
#pragma unroll
                    for (int q = 0; q < 4; q++) {
                        float4 v = *(const float4*)&wr[q * 4];
                        int kk = kh + q * 4;
                        sW[(kk + 0) * 132 + r] = v.x; sW[(kk + 1) * 132 + r] = v.y;
                        sW[(kk + 2) * 132 + r] = v.z; sW[(kk + 3) * 132 + r] = v.w;
                    }
                }
                __syncthreads();
#pragma unroll
                for (int k = 0; k < 32; k++) {
                    float4 w = *(const float4*)&sW[k * 132 + tx * 4];
                    if (ROWS == 32) {
                        float4 a4 = *(const float4*)&sA[k * RP + ty * 4];
                        float a[4] = {a4.x, a4.y, a4.z, a4.w};
#pragma unroll
                        for (int i = 0; i < TM; i++) {
                            acc[i][0] += a[i] * w.x; acc[i][1] += a[i] * w.y;
                            acc[i][2] += a[i] * w.z; acc[i][3] += a[i] * w.w;
                        }
                    } else {
                        float a0 = sA[k * RP + ty];
                        acc[0][0] += a0 * w.x; acc[0][1] += a0 * w.y;
                        acc[0][2] += a0 * w.z; acc[0][3] += a0 * w.w;
                    }
                }
            }
        }
        // epilogue: LSTM gate math + ragged mask
        const int j = j0 + tx;
#pragma unroll
        for (int i = 0; i < TM; i++) {
            int m = m0 + ty * TM + i;
            bool masked = lens && (t >= lens[m / NCc]);
            float pi = acc[i][0], pf = acc[i][1], pg = acc[i][2], po = acc[i][3];
            if (bias) { pi += bias[j]; pf += bias[Hh + j]; pg += bias[2*Hh + j]; po += bias[3*Hh + j]; }
            if (xpre) {
                const float* xr = xpre + (long)m * xstride;
                pi += xr[j]; pf += xr[Hh + j]; pg += xr[2*Hh + j]; po += xr[3*Hh + j];
            }
            float cold = cprev[m * Hh + j];
            float cn = sigf(pf) * cold + sigf(pi) * tanhf(pg);
            float hn = sigf(po) * tanhf(cn);
            if (masked) { hn = hprev[m * Hh + j]; cn = cold; }
            hout[m * Hh + j] = hn;
            cout[m * Hh + j] = cn;
        }
    }
}

// ---------------- persistent kernel: entire recurrent section in one launch ----------------
__global__ __launch_bounds__(256, 2)
void recurrent_all(const float* __restrict__ Whh_v1,
                   const float* __restrict__ Wih_v2, const float* __restrict__ Whh_v2,
                   const float* __restrict__ b_v2,
                   const float* __restrict__ Whh_t1,
                   const float* __restrict__ Wih_t2, const float* __restrict__ Whh_t2,
                   const float* __restrict__ b_t2,
                   const int* __restrict__ qlen)
{
    __shared__ float sA[32 * 36];
    __shared__ float sW[32 * 132];
    unsigned phase = 0;

    // ---- video: 2-layer LSTM over 20 frames (batch 64) ----
    for (int t = 0; t < Fr; t++) {
        int in = t & 1, out = in ^ 1;
        lstm_stage<8>(g_vh1[in], Whh_v1, nullptr, nullptr,
                      g_Xv + t * G4, (long)Fr * G4, nullptr,
                      g_vh1[in], g_vc1[in], g_vh1[out], g_vc1[out],
                      nullptr, t, Bb, sA, sW);
        gridsync(phase);
        lstm_stage<8>(g_vh1[out], Wih_v2, g_vh2[in], Whh_v2,
                      nullptr, 0, b_v2,
                      g_vh2[in], g_vc2[in], g_vh2[out], g_vc2[out],
                      nullptr, t, Bb, sA, sW);
        gridsync(phase);
    }

    // ---- broadcast final video states (buffer 0) to 320 text rows ----
    for (int i = blockIdx.x * 256 + threadIdx.x; i < ROWS_T * Hh; i += NBLK * 256) {
        int b = (i >> 9) / NCc, k = i & 511;
        g_th1[0][i] = g_vh1[0][b * Hh + k];
        g_tc1[0][i] = g_vc1[0][b * Hh + k];
        g_th2[0][i] = g_vh2[0][b * Hh + k];
        g_tc2[0][i] = g_vc2[0][b * Hh + k];
    }
    gridsync(phase);

    // ---- text: 2-layer LSTM over 20 words (batch 320, ragged mask) ----
    for (int t = 0; t < Ll; t++) {
        int in = t & 1, out = in ^ 1;
        lstm_stage<32>(g_th1[in], Whh_t1, nullptr, nullptr,
                       g_Xt + (long)t * G4, (long)Ll * G4, nullptr,
                       g_th1[in], g_tc1[in], g_th1[out], g_tc1[out],
                       qlen, t, ROWS_T, sA, sW);
        gridsync(phase);
        lstm_stage<32>(g_th1[out], Wih_t2, g_th2[in], Whh_t2,
                       nullptr, 0, b_t2,
                       g_th2[in], g_tc2[in], g_th2[out], g_tc2[out],
                       qlen, t, ROWS_T, sA, sW);
        gridsync(phase);
    }
}

// ---------------- small helper kernels ----------------
__global__ void init_k() {
    int i = blockIdx.x * blockDim.x + threadIdx.x;
    if (i == 0) { g_barCnt = 0u; g_barGen = 0u; }
    if (i < Bb * Hh) {
        g_vh1[0][i] = 0.f; g_vc1[0][i] = 0.f;
        g_vh2[0][i] = 0.f; g_vc2[0][i] = 0.f;
    }
}

__global__ void embed_gather(const int* __restrict__ q, const float* __restrict__ ew) {
    long i = (long)blockIdx.x * blockDim.x + threadIdx.x;
    if (i < (long)MT * Ed) {
        int r = (int)(i / Ed), k = (int)(i % Ed);
        g_emb[i] = ew[(long)q[r] * Ed + k];
    }
}

// dec collapses: outputs = sT @ (dec2_w @ dec1_w)^T + (dec1_b . dec2_w + dec2_b)
__global__ void dec_prep(const float* __restrict__ d1w, const float* __restrict__ d1b,
                         const float* __restrict__ d2w, const float* __restrict__ d2b) {
    if (blockIdx.x < 4) {
        int k = blockIdx.x * 256 + threadIdx.x;
        float s = 0.f;
        for (int j = 0; j < 2 * Hh; j++) s += d2w[j] * d1w[j * (2 * Hh) + k];
        g_wc[k] = s;
    } else {
        __shared__ float red[256];
        float s = 0.f;
        for (int j = threadIdx.x; j < 2 * Hh; j += 256) s += d1b[j] * d2w[j];
        red[threadIdx.x] = s; __syncthreads();
        for (int o = 128; o > 0; o >>= 1) {
            if (threadIdx.x < o) red[threadIdx.x] += red[threadIdx.x + o];
            __syncthreads();
        }
        if (threadIdx.x == 0) g_bc = red[0] + d2b[0];
    }
}

__global__ void dec_out(float* __restrict__ dout, int wantOut) {
    int warp = (blockIdx.x * blockDim.x + threadIdx.x) >> 5;
    int lane = threadIdx.x & 31;
    if (warp >= ROWS_T) return;
    const float* h1 = &g_th1[0][warp * Hh];
    const float* h2 = &g_th2[0][warp * Hh];
    float s = 0.f;
    for (int k = lane; k < Hh; k += 32) s += h1[k] * g_wc[k] + h2[k] * g_wc[Hh + k];
#pragma unroll
    for (int o = 16; o > 0; o >>= 1) s += __shfl_down_sync(0xffffffffu, s, o);
    if (lane == 0) {
        float v = s + g_bc;
        g_outbuf[warp] = v;
        if (wantOut) dout[warp] = v;
    }
}

__global__ void argmax_k(float* __restrict__ dout, int off) {
    int b = threadIdx.x;
    if (b < Bb) {
        float best = g_outbuf[b * NCc]; int bi = 0;
        for (int nc = 1; nc < NCc; nc++) {
            float v = g_outbuf[b * NCc + nc];
            if (v > best) { best = v; bi = nc; }
        }
        dout[off + b] = (float)bi;
    }
}

// ---------------- launch ----------------
extern "C" void kernel_launch(void* const* d_in, const int* in_sizes, int n_in,
                              void* d_out, int out_size)
{
    const float* vf     = (const float*)d_in[0];
    const int*   q      = (const int*)  d_in[1];
    const int*   qlen   = (const int*)  d_in[2];
    const float* ew     = (const float*)d_in[3];
    const float* Wih_t1 = (const float*)d_in[4];
    const float* Whh_t1 = (const float*)d_in[5];
    const float* b_t1   = (const float*)d_in[6];
    const float* Wih_t2 = (const float*)d_in[7];
    const float* Whh_t2 = (const float*)d_in[8];
    const float* b_t2   = (const float*)d_in[9];
    const float* Wih_v1 = (const float*)d_in[10];
    const float* Whh_v1 = (const float*)d_in[11];
    const float* b_v1   = (const float*)d_in[12];
    const float* Wih_v2 = (const float*)d_in[13];
    const float* Whh_v2 = (const float*)d_in[14];
    const float* b_v2   = (const float*)d_in[15];
    const float* d1w    = (const float*)d_in[16];
    const float* d1b    = (const float*)d_in[17];
    const float* d2w    = (const float*)d_in[18];
    const float* d2b    = (const float*)d_in[19];
    float* dout = (float*)d_out;

    float *Xv, *emb, *Xt;
    cudaGetSymbolAddress((void**)&Xv,  g_Xv);
    cudaGetSymbolAddress((void**)&emb, g_emb);
    cudaGetSymbolAddress((void**)&Xt,  g_Xt);

    // init + big parallel projections
    init_k<<<(Bb*Hh + 255)/256, 256>>>();
    gemm_big<false><<<dim3(G4/128, MV/64), 256>>>(vf, Wih_v1, b_v1, Xv, MV, G4, Cd);
    embed_gather<<<(int)(((long)MT*Ed + 255)/256), 256>>>(q, ew);
    gemm_big<true><<<dim3(G4/128, MT/64), 256>>>(emb, Wih_t1, b_t1, Xt, MT, G4, Ed);

    // entire recurrent section (video 20 steps + broadcast + text 20 steps)
    recurrent_all<<<NBLK, 256>>>(Whh_v1, Wih_v2, Whh_v2, b_v2,
                                 Whh_t1, Wih_t2, Whh_t2, b_t2, qlen);

    // decoder (collapsed linear) + argmax
    dec_prep<<<5, 256>>>(d1w, d1b, d2w, d2b);
    int wantOut = (out_size >= ROWS_T) ? 1 : 0;
    dec_out<<<(ROWS_T*32 + 127)/128, 128>>>(dout, wantOut);
    int predOff = -1;
    if (out_size >= ROWS_T + Bb) predOff = ROWS_T;
    else if (out_size == Bb)     predOff = 0;
    if (predOff >= 0) argmax_k<<<1, 64>>>(dout, predOff);
}

// round 6
// speedup vs baseline: 1.3549x; 1.1102x over previous
#include <cuda_runtime.h>
#include <math.h>

#define Bb   64
#define NCc  5
#define Ll   20
#define Fr   20
#define Cd   8192
#define Ed   300
#define Hh   512
#define G4   (4*Hh)      // 2048
#define ROWS_T (Bb*NCc)  // 320
#define MV   (Bb*Fr)     // 1280
#define MT   (Bb*NCc*Ll) // 6400
#define NBLK 148         // persistent grid; exactly 1 block per SM (wave-1 covers all SMs)

// ---------------- scratch (device globals; no cudaMalloc allowed) ----------------
__device__ float g_Xv[MV * G4];          // video input projections (+b_v1)
__device__ float g_emb[(size_t)MT * Ed]; // gathered embeddings
__device__ float g_Xt[(size_t)MT * G4];  // text input projections (+b_t1)
__device__ float g_vh1[2][Bb*Hh], g_vc1[2][Bb*Hh], g_vh2[2][Bb*Hh], g_vc2[2][Bb*Hh];
__device__ float g_th1[2][ROWS_T*Hh], g_tc1[2][ROWS_T*Hh], g_th2[2][ROWS_T*Hh], g_tc2[2][ROWS_T*Hh];
__device__ float g_wc[2*Hh];
__device__ float g_bc;
__device__ float g_outbuf[ROWS_T];
__device__ unsigned g_barCnt;
__device__ unsigned g_barGen;

__device__ __forceinline__ float sigf(float x){ return 1.0f/(1.0f+expf(-x)); }

// ---------------- software grid barrier (all NBLK blocks resident by construction) ----
__device__ __forceinline__ void gridsync(unsigned& phase) {
    __threadfence();
    __syncthreads();
    if (threadIdx.x == 0) {
        phase++;
        if (atomicAdd(&g_barCnt, 1u) == NBLK - 1u) {
            g_barCnt = 0u;
            __threadfence();
            atomicExch(&g_barGen, phase);
        } else {
            while (atomicAdd(&g_barGen, 0u) < phase) __nanosleep(64);
        }
    }
    __syncthreads();
}

// ---------------- big GEMM:  C[M,N] = A[M,K] @ W[N,K]^T + bias[N] ----------------
// tile 64(M) x 128(N), BK=16, 256 threads, 8x4 register tile, float4 smem reads.
template<bool GUARD>
__global__ __launch_bounds__(256)
void gemm_big(const float* __restrict__ A, const float* __restrict__ W,
              const float* __restrict__ bias, float* __restrict__ C,
              int M, int N, int K)
{
    __shared__ float As[16][68];
    __shared__ float Bs[16][132];
    const int tid = threadIdx.x;
    const int tx = tid & 31, ty = tid >> 5;   // tx: n-group (4 cols), ty: row group (8 rows)
    const int m0 = blockIdx.y * 64, n0 = blockIdx.x * 128;

    float acc[8][4];
#pragma unroll
    for (int i = 0; i < 8; i++)
#pragma unroll
        for (int j = 0; j < 4; j++) acc[i][j] = 0.f;

    const int ktiles = (K + 15) >> 4;
    for (int kt = 0; kt < ktiles; kt++) {
        const int k0 = kt << 4;
        // load A tile 64x16
        {
            int m = tid >> 2, kq = (tid & 3) << 2;
            if (GUARD) {
#pragma unroll
                for (int i = 0; i < 4; i++) {
                    int k = k0 + kq + i;
                    As[kq + i][m] = (k < K) ? A[(long)(m0 + m) * K + k] : 0.f;
                }
            } else {
                float4 v = *(const float4*)&A[(long)(m0 + m) * K + k0 + kq];
                As[kq + 0][m] = v.x; As[kq + 1][m] = v.y;
                As[kq + 2][m] = v.z; As[kq + 3][m] = v.w;
            }
        }
        // load W tile 128x16
        {
            int r = tid >> 1, kh = (tid & 1) << 3;
#pragma unroll
            for (int q = 0; q < 2; q++) {
                int kq = kh + q * 4;
                if (GUARD) {
#pragma unroll
                    for (int i = 0; i < 4; i++) {
                        int k = k0 + kq + i;
                        Bs[kq + i][r] = (k < K) ? W[(long)(n0 + r) * K + k] : 0.f;
                    }
                } else {
                    float4 v = *(const float4*)&W[(long)(n0 + r) * K + k0 + kq];
                    Bs[kq + 0][r] = v.x; Bs[kq + 1][r] = v.y;
                    Bs[kq + 2][r] = v.z; Bs[kq + 3][r] = v.w;
                }
            }
        }
        __syncthreads();
#pragma unroll
        for (int k = 0; k < 16; k++) {
            float4 b4 = *(const float4*)&Bs[k][tx * 4];
            float4 a0 = *(const float4*)&As[k][ty * 8];
            float4 a1 = *(const float4*)&As[k][ty * 8 + 4];
            float a[8] = {a0.x,a0.y,a0.z,a0.w,a1.x,a1.y,a1.z,a1.w};
            float b[4] = {b4.x,b4.y,b4.z,b4.w};
#pragma unroll
            for (int i = 0; i < 8; i++)
#pragma unroll
                for (int j = 0; j < 4; j++) acc[i][j] += a[i] * b[j];
        }
        __syncthreads();
    }
    float4 bv = *(const float4*)&bias[n0 + tx * 4];
#pragma unroll
    for (int i = 0; i < 8; i++) {
        long m = m0 + ty * 8 + i;
        float4 o = make_float4(acc[i][0] + bv.x, acc[i][1] + bv.y,
                               acc[i][2] + bv.z, acc[i][3] + bv.w);
        *(float4*)&C[m * N + n0 + tx * 4] = o;
    }
}

// ---------------- one LSTM layer update, whole grid cooperates ----------------
// gates = A1@W1^T (+ A2@W2^T) (+xpre) (+bias). W row-major [4*512][512].
// Tile: ROWS batch rows x 32 j's x 4 gates (=128 cols). BK=32. sW[k][jloc*4+g].
// Exactly (M/ROWS)*16 tiles; must be <= NBLK. One tile per block -> zero imbalance.
template<int ROWS>
__device__ void lstm_stage(
    const float* __restrict__ A1, const float* __restrict__ W1,
    const float* __restrict__ A2, const float* __restrict__ W2,
    const float* __restrict__ xpre, long xstride,
    const float* __restrict__ bias,
    const float* __restrict__ hprev, const float* __restrict__ cprev,
    float* __restrict__ hout, float* __restrict__ cout,
    const int* __restrict__ lens, int t, int M,
    float* sA, float* sW)
{
    constexpr int TM = ROWS / 8;        // rows per thread (ty covers 8 groups)
    constexpr int RP = ROWS + 4;
    const int tid = threadIdx.x;
    const int tx = tid & 31;      // j within tile
    const int ty = tid >> 5;      // row group
    const int ntiles = (M / ROWS) * 16;   // row-tiles x 16 j-tiles
    const int tile = blockIdx.x;
    if (tile >= ntiles) return;

    const int m0 = (tile >> 4) * ROWS;
    const int j0 = (tile & 15) * 32;

    // tile skip: all rows masked -> pure state copy (uniform across block)
    if (lens) {
        bool skip = true;
        for (int b = m0 / NCc; b <= (m0 + ROWS - 1) / NCc; b++)
            if (t < lens[b]) { skip = false; break; }
        if (skip) {
            for (int i = tid; i < ROWS * 32; i += 256) {
                int mm = m0 + (i >> 5), jj = j0 + (i & 31);
                hout[mm * Hh + jj] = hprev[mm * Hh + jj];
                cout[mm * Hh + jj] = cprev[mm * Hh + jj];
            }
            return;
        }
    }

    float acc[TM][4];
#pragma unroll
    for (int i = 0; i < TM; i++)
#pragma unroll
        for (int g = 0; g < 4; g++) acc[i][g] = 0.f;

    for (int ph = 0; ph < 2; ph++) {
        const float* Ap = ph ? A2 : A1;
        const float* Wp = ph ? W2 : W1;
        if (ph && A2 == nullptr) break;
        for (int kt = 0; kt < 16; kt++) {
            const int k0 = kt << 5;
            __syncthreads();
            // A tile: ROWS x 32 -> sA[k*RP + m]  (coalesced: 32 consecutive k per row)
#pragma unroll
            for (int i = 0; i < (ROWS * 32) / 256; i++) {
                int idx = tid + i * 256;
                int m = idx >> 5, k = idx & 31;
                sA[k * RP + m] = Ap[(m0 + m) * Hh + k0 + k];
            }
            // W tile: 128 cols (32 j x 4 gates) x 32 k -> sW[k*132 + jloc*4+g]
            {
                int r = tid >> 1, kh = (tid & 1) << 4;
                int j = r >> 2, g = r & 3;
                const float* wr = Wp + (g * Hh + j0 + j) * Hh + k0 + kh;
#pragma unroll
                for (int q = 0; q < 4; q++) {
                    float4 v = *(const float4*)&wr[q * 4];
                    int kk = kh + q * 4;
                    sW[(kk + 0) * 132 + r] = v.x; sW[(kk + 1) * 132 + r] = v.y;
                    sW[(kk + 2) * 132 + r] = v.z; sW[(kk + 3) * 132 + r] = v.w;
                }
            }
            __syncthreads();
#pragma unroll
            for (int k = 0; k < 32; k++) {
                float4 w = *(const float4*)&sW[k * 132 + tx * 4];
#pragma unroll
                for (int i = 0; i < TM; i++) {
                    float a = sA[k * RP + ty * TM + i];
                    acc[i][0] += a * w.x; acc[i][1] += a * w.y;
                    acc[i][2] += a * w.z; acc[i][3] += a * w.w;
                }
            }
        }
    }
    // epilogue: LSTM gate math + ragged mask
    const int j = j0 + tx;
#pragma unroll
    for (int i = 0; i < TM; i++) {
        int m = m0 + ty * TM + i;
        bool masked = lens && (t >= lens[m / NCc]);
        float pi = acc[i][0], pf = acc[i][1], pg = acc[i][2], po = acc[i][3];
        if (bias) { pi += bias[j]; pf += bias[Hh + j]; pg += bias[2*Hh + j]; po += bias[3*Hh + j]; }
        if (xpre) {
            const float* xr = xpre + (long)m * xstride;
            pi += xr[j]; pf += xr[Hh + j]; pg += xr[2*Hh + j]; po += xr[3*Hh + j];
        }
        float cold = cprev[m * Hh + j];
        float cn = sigf(pf) * cold + sigf(pi) * tanhf(pg);
        float hn = sigf(po) * tanhf(cn);
        if (masked) { hn = hprev[m * Hh + j]; cn = cold; }
        hout[m * Hh + j] = hn;
        cout[m * Hh + j] = cn;
    }
}

// ---------------- persistent kernel: entire recurrent section in one launch ----------------
// Text: ROWS=40 -> (320/40)*16 = 128 tiles. Video: ROWS=8 -> (64/8)*16 = 128 tiles.
// 128 <= NBLK=148; one tile per block, no SM does double work, no stragglers.
__global__ __launch_bounds__(256, 2)
void recurrent_all(const float* __restrict__ Whh_v1,
                   const float* __restrict__ Wih_v2, const float* __restrict__ Whh_v2,
                   const float* __restrict__ b_v2,
                   const float* __restrict__ Whh_t1,
                   const float* __restrict__ Wih_t2, const float* __restrict__ Whh_t2,
                   const float* __restrict__ b_t2,
                   const int* __restrict__ qlen)
{
    __shared__ float sA[32 * 44];    // max ROWS=40 -> RP=44
    __shared__ float sW[32 * 132];
    unsigned phase = 0;

    // ---- video: 2-layer LSTM over 20 frames (batch 64) ----
    for (int t = 0; t < Fr; t++) {
        int in = t & 1, out = in ^ 1;
        lstm_stage<8>(g_vh1[in], Whh_v1, nullptr, nullptr,
                      g_Xv + t * G4, (long)Fr * G4, nullptr,
                      g_vh1[in], g_vc1[in], g_vh1[out], g_vc1[out],
                      nullptr, t, Bb, sA, sW);
        gridsync(phase);
        lstm_stage<8>(g_vh1[out], Wih_v2, g_vh2[in], Whh_v2,
                      nullptr, 0, b_v2,
                      g_vh2[in], g_vc2[in], g_vh2[out], g_vc2[out],
                      nullptr, t, Bb, sA, sW);
        gridsync(phase);
    }

    // ---- broadcast final video states (buffer 0) to 320 text rows ----
    for (int i = blockIdx.x * 256 + threadIdx.x; i < ROWS_T * Hh; i += NBLK * 256) {
        int b = (i >> 9) / NCc, k = i & 511;
        g_th1[0][i] = g_vh1[0][b * Hh + k];
        g_tc1[0][i] = g_vc1[0][b * Hh + k];
        g_th2[0][i] = g_vh2[0][b * Hh + k];
        g_tc2[0][i] = g_vc2[0][b * Hh + k];
    }
    gridsync(phase);

    // ---- text: 2-layer LSTM over 20 words (batch 320, ragged mask) ----
    for (int t = 0; t < Ll; t++) {
        int in = t & 1, out = in ^ 1;
        lstm_stage<40>(g_th1[in], Whh_t1, nullptr, nullptr,
                       g_Xt + (long)t * G4, (long)Ll * G4, nullptr,
                       g_th1[in], g_tc1[in], g_th1[out], g_tc1[out],
                       qlen, t, ROWS_T, sA, sW);
        gridsync(phase);
        lstm_stage<40>(g_th1[out], Wih_t2, g_th2[in], Whh_t2,
                       nullptr, 0, b_t2,
                       g_th2[in], g_tc2[in], g_th2[out], g_tc2[out],
                       qlen, t, ROWS_T, sA, sW);
        gridsync(phase);
    }
}

// ---------------- small helper kernels ----------------
__global__ void init_k() {
    int i = blockIdx.x * blockDim.x + threadIdx.x;
    if (i == 0) { g_barCnt = 0u; g_barGen = 0u; }
    if (i < Bb * Hh) {
        g_vh1[0][i] = 0.f; g_vc1[0][i] = 0.f;
        g_vh2[0][i] = 0.f; g_vc2[0][i] = 0.f;
    }
}

__global__ void embed_gather(const int* __restrict__ q, const float* __restrict__ ew) {
    long i = (long)blockIdx.x * blockDim.x + threadIdx.x;
    if (i < (long)MT * Ed) {
        int r = (int)(i / Ed), k = (int)(i % Ed);
        g_emb[i] = ew[(long)q[r] * Ed + k];
    }
}

// dec collapses: outputs = sT @ (dec2_w @ dec1_w)^T + (dec1_b . dec2_w + dec2_b)
__global__ void dec_prep(const float* __restrict__ d1w, const float* __restrict__ d1b,
                         const float* __restrict__ d2w, const float* __restrict__ d2b) {
    if (blockIdx.x < 4) {
        int k = blockIdx.x * 256 + threadIdx.x;
        float s = 0.f;
        for (int j = 0; j < 2 * Hh; j++) s += d2w[j] * d1w[j * (2 * Hh) + k];
        g_wc[k] = s;
    } else {
        __shared__ float red[256];
        float s = 0.f;
        for (int j = threadIdx.x; j < 2 * Hh; j += 256) s += d1b[j] * d2w[j];
        red[threadIdx.x] = s; __syncthreads();
        for (int o = 128; o > 0; o >>= 1) {
            if (threadIdx.x < o) red[threadIdx.x] += red[threadIdx.x + o];
            __syncthreads();
        }
        if (threadIdx.x == 0) g_bc = red[0] + d2b[0];
    }
}

__global__ void dec_out(float* __restrict__ dout, int wantOut) {
    int warp = (blockIdx.x * blockDim.x + threadIdx.x) >> 5;
    int lane = threadIdx.x & 31;
    if (warp >= ROWS_T) return;
    const float* h1 = &g_th1[0][warp * Hh];
    const float* h2 = &g_th2[0][warp * Hh];
    float s = 0.f;
    for (int k = lane; k < Hh; k += 32) s += h1[k] * g_wc[k] + h2[k] * g_wc[Hh + k];
#pragma unroll
    for (int o = 16; o > 0; o >>= 1) s += __shfl_down_sync(0xffffffffu, s, o);
    if (lane == 0) {
        float v = s + g_bc;
        g_outbuf[warp] = v;
        if (wantOut) dout[warp] = v;
    }
}

__global__ void argmax_k(float* __restrict__ dout, int off) {
    int b = threadIdx.x;
    if (b < Bb) {
        float best = g_outbuf[b * NCc]; int bi = 0;
        for (int nc = 1; nc < NCc; nc++) {
            float v = g_outbuf[b * NCc + nc];
            if (v > best) { best = v; bi = nc; }
        }
        dout[off + b] = (float)bi;
    }
}

// ---------------- launch ----------------
extern "C" void kernel_launch(void* const* d_in, const int* in_sizes, int n_in,
                              void* d_out, int out_size)
{
    const float* vf     = (const float*)d_in[0];
    const int*   q      = (const int*)  d_in[1];
    const int*   qlen   = (const int*)  d_in[2];
    const float* ew     = (const float*)d_in[3];
    const float* Wih_t1 = (const float*)d_in[4];
    const float* Whh_t1 = (const float*)d_in[5];
    const float* b_t1   = (const float*)d_in[6];
    const float* Wih_t2 = (const float*)d_in[7];
    const float* Whh_t2 = (const float*)d_in[8];
    const float* b_t2   = (const float*)d_in[9];
    const float* Wih_v1 = (const float*)d_in[10];
    const float* Whh_v1 = (const float*)d_in[11];
    const float* b_v1   = (const float*)d_in[12];
    const float* Wih_v2 = (const float*)d_in[13];
    const float* Whh_v2 = (const float*)d_in[14];
    const float* b_v2   = (const float*)d_in[15];
    const float* d1w    = (const float*)d_in[16];
    const float* d1b    = (const float*)d_in[17];
    const float* d2w    = (const float*)d_in[18];
    const float* d2b    = (const float*)d_in[19];
    float* dout = (float*)d_out;

    float *Xv, *emb, *Xt;
    cudaGetSymbolAddress((void**)&Xv,  g_Xv);
    cudaGetSymbolAddress((void**)&emb, g_emb);
    cudaGetSymbolAddress((void**)&Xt,  g_Xt);

    // init + big parallel projections
    init_k<<<(Bb*Hh + 255)/256, 256>>>();
    gemm_big<false><<<dim3(G4/128, MV/64), 256>>>(vf, Wih_v1, b_v1, Xv, MV, G4, Cd);
    embed_gather<<<(int)(((long)MT*Ed + 255)/256), 256>>>(q, ew);
    gemm_big<true><<<dim3(G4/128, MT/64), 256>>>(emb, Wih_t1, b_t1, Xt, MT, G4, Ed);

    // entire recurrent section (video 20 steps + broadcast + text 20 steps)
    recurrent_all<<<NBLK, 256>>>(Whh_v1, Wih_v2, Whh_v2, b_v2,
                                 Whh_t1, Wih_t2, Whh_t2, b_t2, qlen);

    // decoder (collapsed linear) + argmax
    dec_prep<<<5, 256>>>(d1w, d1b, d2w, d2b);
    int wantOut = (out_size >= ROWS_T) ? 1 : 0;
    dec_out<<<(ROWS_T*32 + 127)/128, 128>>>(dout, wantOut);
    int predOff = -1;
    if (out_size >= ROWS_T + Bb) predOff = ROWS_T;
    else if (out_size == Bb)     predOff = 0;
    if (predOff >= 0) argmax_k<<<1, 64>>>(dout, predOff);
}